// round 11
// baseline (speedup 1.0000x reference)
#include <cuda_runtime.h>
#include <cuda_fp16.h>
#include <cstdint>

#define NTH    256
#define KDIM   128
#define TTILE  128

// fp16 fragment-packed weights:
// [slot(25)][kc(4)][kb(2)][wn(4)][nq(2)][lane(32)][pos(4)][half(2)]
// slot = etype*3 + rule, slot 24 = loop weight. Per-slot stride 32KB.
__device__ __half g_wb[25 * 16384];

__device__ __forceinline__ uint32_t smem_u32(const void* p) {
    uint32_t a;
    asm("{ .reg .u64 t; cvta.to.shared.u64 t, %1; cvt.u32.u64 %0, t; }" : "=r"(a) : "l"(p));
    return a;
}
__device__ __forceinline__ uint32_t pk2(float a, float b) {
    __half2 h = __floats2half2_rn(a, b);
    return *reinterpret_cast<uint32_t*>(&h);
}
__device__ __forceinline__ uint32_t hmul2(uint32_t a, uint32_t b) {
    uint32_t d;
    asm("mul.rn.f16x2 %0, %1, %2;" : "=r"(d) : "r"(a), "r"(b));
    return d;
}
__device__ __forceinline__ uint4 ldg128(const uint4* p) {
    uint4 v;
    asm volatile("ld.global.nc.v4.u32 {%0,%1,%2,%3}, [%4];"
                 : "=r"(v.x), "=r"(v.y), "=r"(v.z), "=r"(v.w) : "l"(p));
    return v;
}

// ---- prep: fragment packing + fp16 rounding of all weights ----
__global__ void prep_w(const float* __restrict__ w, const float* __restrict__ lw) {
    int idx = blockIdx.x * blockDim.x + threadIdx.x;
    if (idx >= 25 * 16384) return;
    int s = idx >> 14, rem = idx & 16383;
    int i = rem >> 7, o = rem & 127;              // B[k=i][n=o]
    float v = (s < 24) ? w[(size_t)s * 16384 + i * 128 + o] : lw[i * 128 + o];
    int kc = i >> 5, kb = (i >> 4) & 1, k16 = i & 15;
    int reg = k16 >> 3, kr = k16 & 7;
    int lane = (o & 7) * 4 + (kr >> 1), hi = kr & 1;
    int wn = o >> 5, ni = (o >> 3) & 3, nq = ni >> 1, pos = (ni & 1) * 2 + reg;
    int flat = s * 16384 + kc * 4096 + kb * 2048 + wn * 512 + nq * 256
             + lane * 8 + pos * 2 + hi;
    g_wb[flat] = __float2half_rn(v);
}

// ============================ kernel 1: self loop ============================
__global__ __launch_bounds__(NTH, 2)
void rgcn_self(const float* __restrict__ feat, const float* __restrict__ bias,
               float* __restrict__ out, int T) {
    extern __shared__ char smraw[];
    char* As = smraw;               // 2 x 8KB

    const int n    = blockIdx.x;
    const int t0   = blockIdx.y * TTILE;
    const int tid  = threadIdx.x;
    const int lane = tid & 31;
    const int warp = tid >> 5;
    const int wm   = warp >> 2;
    const int wn   = warp & 3;

    float acc[4][4][4];
#pragma unroll
    for (int mi = 0; mi < 4; mi++)
#pragma unroll
        for (int ni = 0; ni < 4; ni++)
#pragma unroll
            for (int q = 0; q < 4; q++) acc[mi][ni][q] = 0.f;

    const uint32_t As_u = smem_u32(As);
    const uint4* bgw = (const uint4*)g_wb + (size_t)24 * 2048 + wn * 64 + lane;
    float4 fr[4];

    auto a_load = [&](int kc) {
        const float4* fp = (const float4*)(feat + ((size_t)n * T + t0 + (tid >> 1)) * KDIM
                                           + kc * 32 + (tid & 1) * 16);
        fr[0] = fp[0]; fr[1] = fp[1]; fr[2] = fp[2]; fr[3] = fp[3];
    };
    auto a_store = [&](int buf) {
        char* ab = As + buf * 8192;
        uint4 p0, p1;
        p0.x = pk2(fr[0].x, fr[0].y); p0.y = pk2(fr[0].z, fr[0].w);
        p0.z = pk2(fr[1].x, fr[1].y); p0.w = pk2(fr[1].z, fr[1].w);
        p1.x = pk2(fr[2].x, fr[2].y); p1.y = pk2(fr[2].z, fr[2].w);
        p1.z = pk2(fr[3].x, fr[3].y); p1.w = pk2(fr[3].z, fr[3].w);
        uint32_t off0 = (uint32_t)((tid >> 1) * 64 + (tid & 1) * 32);
        uint32_t off1 = off0 + 16;
        *(uint4*)(ab + (off0 ^ ((off0 >> 3) & 0x30))) = p0;
        *(uint4*)(ab + (off1 ^ ((off1 >> 3) & 0x30))) = p1;
    };
    auto comp = [&](int buf, int kc) {
        const uint32_t ab_u = As_u + buf * 8192;
        const uint4* bg = bgw + (size_t)kc * 512;
        uint4 c0 = ldg128(bg), c1 = ldg128(bg + 32);      // kb=0
#pragma unroll
        for (int kb = 0; kb < 2; kb++) {
            uint32_t a[4][4];
#pragma unroll
            for (int mi = 0; mi < 4; mi++) {
                int tl = wm * 64 + mi * 16 + ((lane >> 3) & 1) * 8 + (lane & 7);
                uint32_t off = (uint32_t)(tl * 64 + (kb * 2 + (lane >> 4)) * 16);
                off ^= (off >> 3) & 0x30;
                asm volatile("ldmatrix.sync.aligned.m8n8.x4.shared.b16 {%0,%1,%2,%3}, [%4];"
                    : "=r"(a[mi][0]), "=r"(a[mi][1]), "=r"(a[mi][2]), "=r"(a[mi][3])
                    : "r"(ab_u + off));
            }
            uint4 n0, n1;
            if (kb == 0) { n0 = ldg128(bg + 256); n1 = ldg128(bg + 256 + 32); }
#pragma unroll
            for (int mi = 0; mi < 4; mi++)
#pragma unroll
                for (int ni = 0; ni < 4; ni++) {
                    uint4 bq = (ni >> 1) ? c1 : c0;
                    uint32_t b0 = (ni & 1) ? bq.z : bq.x;
                    uint32_t b1 = (ni & 1) ? bq.w : bq.y;
                    asm volatile(
                        "mma.sync.aligned.m16n8k16.row.col.f32.f16.f16.f32 "
                        "{%0,%1,%2,%3},{%4,%5,%6,%7},{%8,%9},{%0,%1,%2,%3};"
                        : "+f"(acc[mi][ni][0]), "+f"(acc[mi][ni][1]),
                          "+f"(acc[mi][ni][2]), "+f"(acc[mi][ni][3])
                        : "r"(a[mi][0]), "r"(a[mi][1]), "r"(a[mi][2]), "r"(a[mi][3]),
                          "r"(b0), "r"(b1));
                }
            c0 = n0; c1 = n1;
        }
    };

    a_load(0);
    a_store(0);
    __syncthreads();
    for (int c = 0; c < 4; c++) {
        int buf = c & 1;
        if (c < 3) a_load(c + 1);
        comp(buf, c);
        if (c < 3) a_store(buf ^ 1);
        __syncthreads();
    }

    const int row_base = wm * 64 + (lane >> 2);
    const int col_base = wn * 32 + (lane & 3) * 2;
#pragma unroll
    for (int mi = 0; mi < 4; mi++) {
        float* o0 = out + ((size_t)n * T + t0 + row_base + mi * 16) * KDIM;
#pragma unroll
        for (int ni = 0; ni < 4; ni++) {
            int col = col_base + ni * 8;
            float2 bv = *(const float2*)(bias + col);
            float2 v0 = {acc[mi][ni][0] + bv.x, acc[mi][ni][1] + bv.y};
            float2 v1 = {acc[mi][ni][2] + bv.x, acc[mi][ni][3] + bv.y};
            *(float2*)(o0 + col)            = v0;
            *(float2*)(o0 + 8 * KDIM + col) = v1;
        }
    }
}

// ============================ kernel 2: edges ============================
__global__ __launch_bounds__(NTH, 2)
void rgcn_edge(const float* __restrict__ feat, const float* __restrict__ truth,
               const int* __restrict__ src_idx, const int* __restrict__ dst_idx,
               const int* __restrict__ etypes, float* __restrict__ out, int T) {
    extern __shared__ char smraw[];
    char*     As  = smraw;                       // 2 x 8KB
    uint32_t* tvs = (uint32_t*)(smraw + 16384);  // 3 x 128 half2-bcast

    const int e    = blockIdx.x;
    const int t0   = blockIdx.y * TTILE;
    const int tid  = threadIdx.x;
    const int lane = tid & 31;
    const int warp = tid >> 5;
    const int wm   = warp >> 2;
    const int wn   = warp & 3;

    const int src  = src_idx[e];
    const int dstn = dst_idx[e];
    const int slot = etypes[e] * 3;

    if (tid < TTILE) {
        const float* tp = truth + ((size_t)e * T + t0 + tid) * 3;
        tvs[tid]       = pk2(tp[0], tp[0]);
        tvs[128 + tid] = pk2(tp[1], tp[1]);
        tvs[256 + tid] = pk2(tp[2], tp[2]);
    }

    float acc[4][4][4];
#pragma unroll
    for (int mi = 0; mi < 4; mi++)
#pragma unroll
        for (int ni = 0; ni < 4; ni++)
#pragma unroll
            for (int q = 0; q < 4; q++) acc[mi][ni][q] = 0.f;

    const uint32_t As_u = smem_u32(As);
    const uint4* bgw = (const uint4*)g_wb + (size_t)slot * 2048 + wn * 64 + lane;
    float4 fr[4];

    auto a_load = [&](int kc) {
        const float4* fp = (const float4*)(feat + ((size_t)src * T + t0 + (tid >> 1)) * KDIM
                                           + kc * 32 + (tid & 1) * 16);
        fr[0] = fp[0]; fr[1] = fp[1]; fr[2] = fp[2]; fr[3] = fp[3];
    };
    auto a_store = [&](int buf) {
        char* ab = As + buf * 8192;
        uint4 p0, p1;
        p0.x = pk2(fr[0].x, fr[0].y); p0.y = pk2(fr[0].z, fr[0].w);
        p0.z = pk2(fr[1].x, fr[1].y); p0.w = pk2(fr[1].z, fr[1].w);
        p1.x = pk2(fr[2].x, fr[2].y); p1.y = pk2(fr[2].z, fr[2].w);
        p1.z = pk2(fr[3].x, fr[3].y); p1.w = pk2(fr[3].z, fr[3].w);
        uint32_t off0 = (uint32_t)((tid >> 1) * 64 + (tid & 1) * 32);
        uint32_t off1 = off0 + 16;
        *(uint4*)(ab + (off0 ^ ((off0 >> 3) & 0x30))) = p0;
        *(uint4*)(ab + (off1 ^ ((off1 >> 3) & 0x30))) = p1;
    };

    auto comp = [&](int buf, int kc) {
        const uint32_t ab_u = As_u + buf * 8192;
        const uint4* bg = bgw + (size_t)kc * 512;
        // flat (kb, r) phase pipeline, 1 phase ahead: off = kb*256 + r*2048 (uint4)
        uint4 c0 = ldg128(bg), c1 = ldg128(bg + 32);     // phase 0 = (kb0, r0)
#pragma unroll
        for (int kb = 0; kb < 2; kb++) {
            uint32_t a[4][4];
#pragma unroll
            for (int mi = 0; mi < 4; mi++) {
                int tl = wm * 64 + mi * 16 + ((lane >> 3) & 1) * 8 + (lane & 7);
                uint32_t off = (uint32_t)(tl * 64 + (kb * 2 + (lane >> 4)) * 16);
                off ^= (off >> 3) & 0x30;
                asm volatile("ldmatrix.sync.aligned.m8n8.x4.shared.b16 {%0,%1,%2,%3}, [%4];"
                    : "=r"(a[mi][0]), "=r"(a[mi][1]), "=r"(a[mi][2]), "=r"(a[mi][3])
                    : "r"(ab_u + off));
            }
#pragma unroll
            for (int r = 0; r < 3; r++) {
                int p = kb * 3 + r;
                uint4 n0, n1;
                if (p < 5) {
                    int np = p + 1, nkb = (np >= 3), nr = np - nkb * 3;
                    const uint4* bp = bg + nkb * 256 + nr * 2048;
                    n0 = ldg128(bp); n1 = ldg128(bp + 32);
                }
#pragma unroll
                for (int mi = 0; mi < 4; mi++) {
                    int row = wm * 64 + mi * 16 + (lane >> 2);
                    uint32_t tlo = tvs[r * 128 + row];
                    uint32_t thi = tvs[r * 128 + row + 8];
                    uint32_t am0 = hmul2(a[mi][0], tlo), am1 = hmul2(a[mi][1], thi);
                    uint32_t am2 = hmul2(a[mi][2], tlo), am3 = hmul2(a[mi][3], thi);
#pragma unroll
                    for (int ni = 0; ni < 4; ni++) {
                        uint4 bq = (ni >> 1) ? c1 : c0;
                        uint32_t b0 = (ni & 1) ? bq.z : bq.x;
                        uint32_t b1 = (ni & 1) ? bq.w : bq.y;
                        asm volatile(
                            "mma.sync.aligned.m16n8k16.row.col.f32.f16.f16.f32 "
                            "{%0,%1,%2,%3},{%4,%5,%6,%7},{%8,%9},{%0,%1,%2,%3};"
                            : "+f"(acc[mi][ni][0]), "+f"(acc[mi][ni][1]),
                              "+f"(acc[mi][ni][2]), "+f"(acc[mi][ni][3])
                            : "r"(am0), "r"(am1), "r"(am2), "r"(am3),
                              "r"(b0), "r"(b1));
                    }
                }
                c0 = n0; c1 = n1;
            }
        }
    };

    a_load(0);
    a_store(0);
    __syncthreads();
    for (int c = 0; c < 4; c++) {
        int buf = c & 1;
        if (c < 3) a_load(c + 1);
        comp(buf, c);
        if (c < 3) a_store(buf ^ 1);
        __syncthreads();
    }

    // RED-accumulate message tile into out[dst]
    const int row_base = wm * 64 + (lane >> 2);
    const int col_base = wn * 32 + (lane & 3) * 2;
#pragma unroll
    for (int mi = 0; mi < 4; mi++) {
        float* o0 = out + ((size_t)dstn * T + t0 + row_base + mi * 16) * KDIM;
#pragma unroll
        for (int ni = 0; ni < 4; ni++) {
            int col = col_base + ni * 8;
            asm volatile("red.global.add.v2.f32 [%0], {%1,%2};"
                         :: "l"(o0 + col), "f"(acc[mi][ni][0]), "f"(acc[mi][ni][1]) : "memory");
            asm volatile("red.global.add.v2.f32 [%0], {%1,%2};"
                         :: "l"(o0 + 8 * KDIM + col), "f"(acc[mi][ni][2]), "f"(acc[mi][ni][3]) : "memory");
        }
    }
}

// ---------------- launch ----------------
extern "C" void kernel_launch(void* const* d_in, const int* in_sizes, int n_in,
                              void* d_out, int out_size) {
    const float* feat   = (const float*)d_in[0];
    const float* truth  = (const float*)d_in[1];
    const float* weight = (const float*)d_in[2];
    const float* loop_w = (const float*)d_in[3];
    const float* bias   = (const float*)d_in[4];
    const int*   src    = (const int*)d_in[5];
    const int*   dst    = (const int*)d_in[6];
    const int*   etyp   = (const int*)d_in[7];
    float*       out    = (float*)d_out;

    const int E = in_sizes[5];
    const int T = in_sizes[1] / (E * 3);
    const int N = in_sizes[0] / (T * KDIM);

    prep_w<<<(25 * 16384 + 255) / 256, 256>>>(weight, loop_w);

    size_t smem_s = 16384;
    cudaFuncSetAttribute(rgcn_self, cudaFuncAttributeMaxDynamicSharedMemorySize, (int)smem_s);
    rgcn_self<<<dim3(N, T / TTILE), NTH, smem_s>>>(feat, bias, out, T);

    size_t smem_e = 16384 + 384 * 4;
    cudaFuncSetAttribute(rgcn_edge, cudaFuncAttributeMaxDynamicSharedMemorySize, (int)smem_e);
    rgcn_edge<<<dim3(E, T / TTILE), NTH, smem_e>>>(feat, truth, src, dst, etyp, out, T);
}

// round 14
// speedup vs baseline: 1.2957x; 1.2957x over previous
#include <cuda_runtime.h>
#include <cuda_fp16.h>
#include <cstdint>

#define NTH    256
#define KDIM   128
#define TTILE  128

// fp16 fragment-packed weights:
// [slot(25)][kc(4)][wn(4)][kb(2)][nq(2)][lane(32)][pos(4)][half(2)]
// slot = etype*3 + rule, slot 24 = loop weight. 2KB per (slot,kc,wn) slice.
__device__ __half g_wb[25 * 16384];

__device__ __forceinline__ uint32_t smem_u32(const void* p) {
    uint32_t a;
    asm("{ .reg .u64 t; cvta.to.shared.u64 t, %1; cvt.u32.u64 %0, t; }" : "=r"(a) : "l"(p));
    return a;
}
__device__ __forceinline__ uint32_t pk2(float a, float b) {
    __half2 h = __floats2half2_rn(a, b);
    return *reinterpret_cast<uint32_t*>(&h);
}
__device__ __forceinline__ uint32_t hmul2(uint32_t a, uint32_t b) {
    uint32_t d;
    asm("mul.rn.f16x2 %0, %1, %2;" : "=r"(d) : "r"(a), "r"(b));
    return d;
}

// ---- prep: fragment packing + fp16 rounding of all weights ----
__global__ void prep_w(const float* __restrict__ w, const float* __restrict__ lw) {
    int idx = blockIdx.x * blockDim.x + threadIdx.x;
    if (idx >= 25 * 16384) return;
    int s = idx >> 14, rem = idx & 16383;
    int i = rem >> 7, o = rem & 127;              // B[k=i][n=o]
    float v = (s < 24) ? w[(size_t)s * 16384 + i * 128 + o] : lw[i * 128 + o];
    int kc = i >> 5, kb = (i >> 4) & 1, k16 = i & 15;
    int reg = k16 >> 3, kr = k16 & 7;
    int lane = (o & 7) * 4 + (kr >> 1), hi = kr & 1;
    int wn = o >> 5, ni = (o >> 3) & 3, nq = ni >> 1, pos = (ni & 1) * 2 + reg;
    int flat = s * 16384 + kc * 4096 + wn * 1024 + kb * 512 + nq * 256
             + lane * 8 + pos * 2 + hi;
    g_wb[flat] = __float2half_rn(v);
}

// shared A-fill: whole 128x128 tile into 4 SW64 chunks (one barrier afterwards)
__device__ __forceinline__ void fill_A(const float* __restrict__ feat, int node,
                                       int t0, int T, char* As, int tid) {
    int row = tid >> 1, hk = tid & 1;
    const float* base = feat + ((size_t)node * T + t0 + row) * KDIM + hk * 16;
#pragma unroll
    for (int kc = 0; kc < 4; kc++) {
        const float4* fp = (const float4*)(base + kc * 32);
        float4 f0 = fp[0], f1 = fp[1], f2 = fp[2], f3 = fp[3];
        uint4 p0, p1;
        p0.x = pk2(f0.x, f0.y); p0.y = pk2(f0.z, f0.w);
        p0.z = pk2(f1.x, f1.y); p0.w = pk2(f1.z, f1.w);
        p1.x = pk2(f2.x, f2.y); p1.y = pk2(f2.z, f2.w);
        p1.z = pk2(f3.x, f3.y); p1.w = pk2(f3.z, f3.w);
        uint32_t off0 = (uint32_t)(row * 64 + hk * 32);
        uint32_t off1 = off0 + 16;
        char* ab = As + kc * 8192;
        *(uint4*)(ab + (off0 ^ ((off0 >> 3) & 0x30))) = p0;
        *(uint4*)(ab + (off1 ^ ((off1 >> 3) & 0x30))) = p1;
    }
}

// per-warp 2KB B-slice fill via cp.async (no commit here)
__device__ __forceinline__ void fill_B(uint32_t dst, int slot, int kc, int wn, int lane) {
    const char* gs = (const char*)g_wb
                   + ((size_t)slot * 16384 + kc * 4096 + wn * 1024) * 2;
#pragma unroll
    for (int u = 0; u < 4; u++) {
        uint32_t boff = (uint32_t)((u * 32 + lane) * 16);
        asm volatile("cp.async.cg.shared.global [%0], [%1], 16;"
                     :: "r"(dst + boff), "l"(gs + boff));
    }
}
#define CPCOMMIT() asm volatile("cp.async.commit_group;" ::: "memory")
#define CPWAIT(n)  asm volatile("cp.async.wait_group %0;" :: "n"(n) : "memory")

#define LDMA(dst, addr)                                                                  \
    asm volatile("ldmatrix.sync.aligned.m8n8.x4.shared.b16 {%0,%1,%2,%3}, [%4];"         \
        : "=r"((dst)[0]), "=r"((dst)[1]), "=r"((dst)[2]), "=r"((dst)[3]) : "r"(addr))

#define HMMA(acc, a0, a1, a2, a3, b0, b1)                                                \
    asm volatile("mma.sync.aligned.m16n8k16.row.col.f32.f16.f16.f32 "                    \
        "{%0,%1,%2,%3},{%4,%5,%6,%7},{%8,%9},{%0,%1,%2,%3};"                             \
        : "+f"((acc)[0]), "+f"((acc)[1]), "+f"((acc)[2]), "+f"((acc)[3])                  \
        : "r"(a0), "r"(a1), "r"(a2), "r"(a3), "r"(b0), "r"(b1))

// ============================ kernel 1: self loop ============================
// B: per-WARP private, 2 stages x 2KB -> Bs + warp*4096 + stage*2048  (32KB)
__global__ __launch_bounds__(NTH, 2)
void rgcn_self(const float* __restrict__ feat, const float* __restrict__ bias,
               float* __restrict__ out, int T) {
    extern __shared__ char smraw[];
    char* As = smraw;                 // 32KB
    char* Bs = smraw + 32768;         // 32KB

    const int n    = blockIdx.x;
    const int t0   = blockIdx.y * TTILE;
    const int tid  = threadIdx.x;
    const int lane = tid & 31;
    const int warp = tid >> 5;
    const int wm   = warp >> 2;
    const int wn   = warp & 3;

    float acc[4][4][4];
#pragma unroll
    for (int mi = 0; mi < 4; mi++)
#pragma unroll
        for (int ni = 0; ni < 4; ni++)
#pragma unroll
            for (int q = 0; q < 4; q++) acc[mi][ni][q] = 0.f;

    const uint32_t As_u = smem_u32(As);
    const uint32_t Bw_u = smem_u32(Bs) + warp * 4096;

    fill_B(Bw_u, 24, 0, wn, lane);
    CPCOMMIT();
    fill_A(feat, n, t0, T, As, tid);
    __syncthreads();

#pragma unroll
    for (int kc = 0; kc < 4; kc++) {
        int stage = kc & 1;
        if (kc < 3) {
            fill_B(Bw_u + (stage ^ 1) * 2048, 24, kc + 1, wn, lane);
            CPCOMMIT();
            CPWAIT(1);
        } else {
            CPWAIT(0);
        }

        uint32_t a2[2][4][4];
#pragma unroll
        for (int kb = 0; kb < 2; kb++)
#pragma unroll
            for (int mi = 0; mi < 4; mi++) {
                int tl = wm * 64 + mi * 16 + ((lane >> 3) & 1) * 8 + (lane & 7);
                uint32_t off = (uint32_t)(tl * 64 + (kb * 2 + (lane >> 4)) * 16);
                off ^= (off >> 3) & 0x30;
                LDMA(a2[kb][mi], As_u + kc * 8192 + off);
            }
        const uint4* bu = (const uint4*)(Bs + warp * 4096 + stage * 2048);
        uint4 bq[2][2];
        bq[0][0] = bu[lane];      bq[0][1] = bu[32 + lane];
        bq[1][0] = bu[64 + lane]; bq[1][1] = bu[96 + lane];
#pragma unroll
        for (int kb = 0; kb < 2; kb++)
#pragma unroll
            for (int mi = 0; mi < 4; mi++)
#pragma unroll
                for (int ni = 0; ni < 4; ni++) {
                    uint4 q = bq[kb][ni >> 1];
                    HMMA(acc[mi][ni], a2[kb][mi][0], a2[kb][mi][1], a2[kb][mi][2], a2[kb][mi][3],
                         (ni & 1) ? q.z : q.x, (ni & 1) ? q.w : q.y);
                }
    }

    const int row_base = wm * 64 + (lane >> 2);
    const int col_base = wn * 32 + (lane & 3) * 2;
#pragma unroll
    for (int mi = 0; mi < 4; mi++) {
        float* o0 = out + ((size_t)n * T + t0 + row_base + mi * 16) * KDIM;
#pragma unroll
        for (int ni = 0; ni < 4; ni++) {
            int col = col_base + ni * 8;
            float2 bv = *(const float2*)(bias + col);
            float2 v0 = {acc[mi][ni][0] + bv.x, acc[mi][ni][1] + bv.y};
            float2 v1 = {acc[mi][ni][2] + bv.x, acc[mi][ni][3] + bv.y};
            *(float2*)(o0 + col)            = v0;
            *(float2*)(o0 + 8 * KDIM + col) = v1;
        }
    }
}

// ============================ kernel 2: edges ============================
// B: per-WARP private, 2 stages x 2KB; 12 flat phases p=(kc,r) stream through.
__global__ __launch_bounds__(NTH, 2)
void rgcn_edge(const float* __restrict__ feat, const float* __restrict__ truth,
               const int* __restrict__ src_idx, const int* __restrict__ dst_idx,
               const int* __restrict__ etypes, float* __restrict__ out, int T) {
    extern __shared__ char smraw[];
    char*     As  = smraw;                       // 32KB
    char*     Bs  = smraw + 32768;               // 32KB (8 warps x 2 x 2KB)
    uint32_t* tvs = (uint32_t*)(smraw + 65536);  // 3 x 128 half2-bcast

    const int e    = blockIdx.x;
    const int t0   = blockIdx.y * TTILE;
    const int tid  = threadIdx.x;
    const int lane = tid & 31;
    const int warp = tid >> 5;
    const int wm   = warp >> 2;
    const int wn   = warp & 3;

    const int src  = src_idx[e];
    const int dstn = dst_idx[e];
    const int slot = etypes[e] * 3;

    float acc[4][4][4];
#pragma unroll
    for (int mi = 0; mi < 4; mi++)
#pragma unroll
        for (int ni = 0; ni < 4; ni++)
#pragma unroll
            for (int q = 0; q < 4; q++) acc[mi][ni][q] = 0.f;

    const uint32_t As_u = smem_u32(As);
    const uint32_t Bw_u = smem_u32(Bs) + warp * 4096;

    // prologue: phase 0 = (kc0, r0)
    fill_B(Bw_u, slot, 0, wn, lane);
    CPCOMMIT();

    if (tid < TTILE) {
        const float* tp = truth + ((size_t)e * T + t0 + tid) * 3;
        tvs[tid]       = pk2(tp[0], tp[0]);
        tvs[128 + tid] = pk2(tp[1], tp[1]);
        tvs[256 + tid] = pk2(tp[2], tp[2]);
    }
    fill_A(feat, src, t0, T, As, tid);
    __syncthreads();

    uint32_t a2[2][4][4];
#pragma unroll
    for (int p = 0; p < 12; p++) {
        const int buf = p & 1;
        const int kc = p / 3, r = p % 3;
        if (p < 11) {
            const int np = p + 1;
            fill_B(Bw_u + (buf ^ 1) * 2048, slot + np % 3, np / 3, wn, lane);
            CPCOMMIT();
            CPWAIT(1);
        } else {
            CPWAIT(0);
        }

        if (r == 0) {       // new kc: refresh A fragments (reused for 3 rules)
#pragma unroll
            for (int kb = 0; kb < 2; kb++)
#pragma unroll
                for (int mi = 0; mi < 4; mi++) {
                    int tl = wm * 64 + mi * 16 + ((lane >> 3) & 1) * 8 + (lane & 7);
                    uint32_t off = (uint32_t)(tl * 64 + (kb * 2 + (lane >> 4)) * 16);
                    off ^= (off >> 3) & 0x30;
                    LDMA(a2[kb][mi], As_u + kc * 8192 + off);
                }
        }

        const uint4* bu = (const uint4*)(Bs + warp * 4096 + buf * 2048);
        uint4 bq[2][2];
        bq[0][0] = bu[lane];      bq[0][1] = bu[32 + lane];
        bq[1][0] = bu[64 + lane]; bq[1][1] = bu[96 + lane];
#pragma unroll
        for (int kb = 0; kb < 2; kb++)
#pragma unroll
            for (int mi = 0; mi < 4; mi++) {
                int row = wm * 64 + mi * 16 + (lane >> 2);
                uint32_t tlo = tvs[r * 128 + row];
                uint32_t thi = tvs[r * 128 + row + 8];
                uint32_t am0 = hmul2(a2[kb][mi][0], tlo), am1 = hmul2(a2[kb][mi][1], thi);
                uint32_t am2 = hmul2(a2[kb][mi][2], tlo), am3 = hmul2(a2[kb][mi][3], thi);
#pragma unroll
                for (int ni = 0; ni < 4; ni++) {
                    uint4 q = bq[kb][ni >> 1];
                    HMMA(acc[mi][ni], am0, am1, am2, am3,
                         (ni & 1) ? q.z : q.x, (ni & 1) ? q.w : q.y);
                }
            }
    }

    // RED-accumulate message tile into out[dst]
    const int row_base = wm * 64 + (lane >> 2);
    const int col_base = wn * 32 + (lane & 3) * 2;
#pragma unroll
    for (int mi = 0; mi < 4; mi++) {
        float* o0 = out + ((size_t)dstn * T + t0 + row_base + mi * 16) * KDIM;
#pragma unroll
        for (int ni = 0; ni < 4; ni++) {
            int col = col_base + ni * 8;
            asm volatile("red.global.add.v2.f32 [%0], {%1,%2};"
                         :: "l"(o0 + col), "f"(acc[mi][ni][0]), "f"(acc[mi][ni][1]) : "memory");
            asm volatile("red.global.add.v2.f32 [%0], {%1,%2};"
                         :: "l"(o0 + 8 * KDIM + col), "f"(acc[mi][ni][2]), "f"(acc[mi][ni][3]) : "memory");
        }
    }
}

// ---------------- launch ----------------
extern "C" void kernel_launch(void* const* d_in, const int* in_sizes, int n_in,
                              void* d_out, int out_size) {
    const float* feat   = (const float*)d_in[0];
    const float* truth  = (const float*)d_in[1];
    const float* weight = (const float*)d_in[2];
    const float* loop_w = (const float*)d_in[3];
    const float* bias   = (const float*)d_in[4];
    const int*   src    = (const int*)d_in[5];
    const int*   dst    = (const int*)d_in[6];
    const int*   etyp   = (const int*)d_in[7];
    float*       out    = (float*)d_out;

    const int E = in_sizes[5];
    const int T = in_sizes[1] / (E * 3);
    const int N = in_sizes[0] / (T * KDIM);

    prep_w<<<(25 * 16384 + 255) / 256, 256>>>(weight, loop_w);

    size_t smem_s = 65536;
    cudaFuncSetAttribute(rgcn_self, cudaFuncAttributeMaxDynamicSharedMemorySize, (int)smem_s);
    rgcn_self<<<dim3(N, T / TTILE), NTH, smem_s>>>(feat, bias, out, T);

    size_t smem_e = 65536 + 1536;
    cudaFuncSetAttribute(rgcn_edge, cudaFuncAttributeMaxDynamicSharedMemorySize, (int)smem_e);
    rgcn_edge<<<dim3(E, T / TTILE), NTH, smem_e>>>(feat, truth, src, dst, etyp, out, T);
}